// round 5
// baseline (speedup 1.0000x reference)
#include <cuda_runtime.h>
#include <cuda_fp16.h>
#include <math.h>
#include <stdint.h>

// ---------------------------------------------------------------------------
// Problem constants
// ---------------------------------------------------------------------------
#define D_MODEL   512
#define D_STATE   128
#define HEADDIM   64
#define D_INNER   1024
#define NHEADS    16
#define CONV_DIM  1280
#define D_IN_PROJ 2320
#define LSEQ      64
#define NSEQ      128
#define NTOK      8192
#define EPS       1e-5f

// ---------------------------------------------------------------------------
// Device scratch
// ---------------------------------------------------------------------------
__device__ float g_zx   [(size_t)NTOK * D_IN_PROJ];
__device__ float g_xbc  [(size_t)NTOK * CONV_DIM];
__device__ float g_y    [(size_t)NTOK * D_INNER];
__device__ float g_cat  [(size_t)NTOK * D_INNER];
__device__ float g_fceff[(size_t)D_MODEL * D_INNER];

// ---------------------------------------------------------------------------
// Helpers
// ---------------------------------------------------------------------------
__device__ __forceinline__ uint32_t smem_u32(const void* p) {
    uint32_t a;
    asm("{ .reg .u64 t; cvta.to.shared.u64 t, %1; cvt.u32.u64 %0, t; }"
        : "=r"(a) : "l"(p));
    return a;
}
#define SWZ128(o) ((o) ^ (((o) >> 3) & 0x70))
#define CP_ASYNC16(dst, src) \
    asm volatile("cp.async.cg.shared.global [%0], [%1], 16;" :: "r"(dst), "l"(src) : "memory")

__device__ __forceinline__ void ldmatrix_x4(uint32_t* r, uint32_t addr) {
    asm volatile("ldmatrix.sync.aligned.m8n8.x4.shared.b16 {%0,%1,%2,%3}, [%4];"
                 : "=r"(r[0]), "=r"(r[1]), "=r"(r[2]), "=r"(r[3]) : "r"(addr));
}
__device__ __forceinline__ void mma_f16(float* d, const uint32_t* a,
                                        uint32_t b0, uint32_t b1) {
    asm volatile(
        "mma.sync.aligned.m16n8k16.row.col.f32.f16.f16.f32 "
        "{%0,%1,%2,%3}, {%4,%5,%6,%7}, {%8,%9}, {%0,%1,%2,%3};"
        : "+f"(d[0]), "+f"(d[1]), "+f"(d[2]), "+f"(d[3])
        : "r"(a[0]), "r"(a[1]), "r"(a[2]), "r"(a[3]), "r"(b0), "r"(b1));
}
// swap the two low 6-bit fields of a token row index ((b,hh,w) <-> (b,w,hh))
__device__ __forceinline__ int swap66(int r) {
    return (r & ~0xFFF) | ((r & 63) << 6) | ((r >> 6) & 63);
}

// ---------------------------------------------------------------------------
// fp32-input split-fp16 GEMM:
//   C[m][n] = sum_k A[m][k] * W[n][k] (+ bias[n]),  A fp32 MxK, W fp32 NxK.
// In-kernel split: A -> (ah + al) fp16, W -> wh fp16; acc = ah*wh + al*wh.
// Tile 128x128, k-step 64 fp32. cp.async double-buffered fp32 staging,
// SMEM convert to SW128 fp16 tiles, ldmatrix + mma.sync.
// Epilogue supports ldc, column offset, and (b,hh,w)->(b,w,hh) row permute.
// permA permutes A source rows the same way (used for v-direction in-proj).
// ---------------------------------------------------------------------------
#define ST_A(s)   ((s) * 65536u)
#define ST_W(s)   ((s) * 65536u + 32768u)
#define F16_AH    131072u
#define F16_AL    (131072u + 16384u)
#define F16_WH    (131072u + 32768u)
#define GSM_TOTAL (131072 + 49152)

__device__ __forceinline__ void gemm_load_stage(
    const float* __restrict__ A, const float* __restrict__ W,
    uint32_t sb, int m0, int n0, int K, int kt, int stage, int tid, int permA)
{
    uint32_t a_dst = sb + ST_A(stage);
    uint32_t w_dst = sb + ST_W(stage);
#pragma unroll
    for (int j = 0; j < 8; ++j) {
        int idx = tid + j * 256;
        int row = idx >> 4, c = idx & 15;
        int ar = m0 + row;
        if (permA) ar = swap66(ar);
        CP_ASYNC16(a_dst + (uint32_t)(row * 256 + c * 16),
                   A + ((size_t)ar * K + kt * 64 + c * 4));
    }
#pragma unroll
    for (int j = 0; j < 8; ++j) {
        int idx = tid + j * 256;
        int row = idx >> 4, c = idx & 15;
        CP_ASYNC16(w_dst + (uint32_t)(row * 256 + c * 16),
                   W + ((size_t)(n0 + row) * K + kt * 64 + c * 4));
    }
}

__device__ __forceinline__ void gemm_convert_stage(uint32_t sb, int stage, int tid)
{
    const float* As = (const float*)(uintptr_t)0;  // unused; use smem via asm-free path
    // A: 128 rows x 64 floats -> A_hi, A_lo
#pragma unroll
    for (int j = 0; j < 8; ++j) {
        int idx = tid + j * 256;
        int row = idx >> 4, c4 = idx & 15;
        float4 v;
        asm volatile("ld.shared.v4.f32 {%0,%1,%2,%3}, [%4];"
                     : "=f"(v.x), "=f"(v.y), "=f"(v.z), "=f"(v.w)
                     : "r"(sb + ST_A(stage) + (uint32_t)(row * 256 + c4 * 16)));
        __half h0 = __float2half_rn(v.x), h1 = __float2half_rn(v.y);
        __half h2 = __float2half_rn(v.z), h3 = __float2half_rn(v.w);
        __half l0 = __float2half_rn(v.x - __half2float(h0));
        __half l1 = __float2half_rn(v.y - __half2float(h1));
        __half l2 = __float2half_rn(v.z - __half2float(h2));
        __half l3 = __float2half_rn(v.w - __half2float(h3));
        uint32_t hh0 = ((uint32_t)__half_as_ushort(h1) << 16) | __half_as_ushort(h0);
        uint32_t hh1 = ((uint32_t)__half_as_ushort(h3) << 16) | __half_as_ushort(h2);
        uint32_t ll0 = ((uint32_t)__half_as_ushort(l1) << 16) | __half_as_ushort(l0);
        uint32_t ll1 = ((uint32_t)__half_as_ushort(l3) << 16) | __half_as_ushort(l2);
        uint32_t off = SWZ128((uint32_t)(row * 128 + c4 * 8));
        asm volatile("st.shared.v2.u32 [%0], {%1,%2};" :: "r"(sb + F16_AH + off), "r"(hh0), "r"(hh1));
        asm volatile("st.shared.v2.u32 [%0], {%1,%2};" :: "r"(sb + F16_AL + off), "r"(ll0), "r"(ll1));
    }
    // W: 128 rows x 64 floats -> W_hi
#pragma unroll
    for (int j = 0; j < 8; ++j) {
        int idx = tid + j * 256;
        int row = idx >> 4, c4 = idx & 15;
        float4 v;
        asm volatile("ld.shared.v4.f32 {%0,%1,%2,%3}, [%4];"
                     : "=f"(v.x), "=f"(v.y), "=f"(v.z), "=f"(v.w)
                     : "r"(sb + ST_W(stage) + (uint32_t)(row * 256 + c4 * 16)));
        __half h0 = __float2half_rn(v.x), h1 = __float2half_rn(v.y);
        __half h2 = __float2half_rn(v.z), h3 = __float2half_rn(v.w);
        uint32_t hh0 = ((uint32_t)__half_as_ushort(h1) << 16) | __half_as_ushort(h0);
        uint32_t hh1 = ((uint32_t)__half_as_ushort(h3) << 16) | __half_as_ushort(h2);
        uint32_t off = SWZ128((uint32_t)(row * 128 + c4 * 8));
        asm volatile("st.shared.v2.u32 [%0], {%1,%2};" :: "r"(sb + F16_WH + off), "r"(hh0), "r"(hh1));
    }
    (void)As;
}

__global__ __launch_bounds__(256)
void gemm_split_kernel(const float* __restrict__ A, const float* __restrict__ W,
                       float* __restrict__ C, int K, int N, int ldc, int col0,
                       const float* __restrict__ bias, int permA, int permC)
{
    extern __shared__ char smem[];
    uint32_t sb = smem_u32(smem);
    const int tid  = threadIdx.x;
    const int wid  = tid >> 5;
    const int lane = tid & 31;
    const int wm   = wid & 1;
    const int wn   = wid >> 1;
    const int m0   = blockIdx.y * 128;
    const int n0   = blockIdx.x * 128;

    float acc[4][4][4];
#pragma unroll
    for (int i = 0; i < 4; ++i)
#pragma unroll
        for (int j = 0; j < 4; ++j) {
            acc[i][j][0] = 0.f; acc[i][j][1] = 0.f;
            acc[i][j][2] = 0.f; acc[i][j][3] = 0.f;
        }

    const int nK = K / 64;
    gemm_load_stage(A, W, sb, m0, n0, K, 0, 0, tid, permA);
    asm volatile("cp.async.commit_group;" ::: "memory");
    gemm_load_stage(A, W, sb, m0, n0, K, 1, 1, tid, permA);
    asm volatile("cp.async.commit_group;" ::: "memory");

    const int lrow = lane & 15;
    const int lcol = (lane >> 4) * 16;

    for (int i = 0; i < nK; ++i) {
        if (i + 1 < nK) asm volatile("cp.async.wait_group 1;" ::: "memory");
        else            asm volatile("cp.async.wait_group 0;" ::: "memory");
        __syncthreads();                       // staging ready; prev mma done
        gemm_convert_stage(sb, i & 1, tid);
        __syncthreads();                       // fp16 tiles ready
        if (i + 2 < nK) {
            gemm_load_stage(A, W, sb, m0, n0, K, i + 2, i & 1, tid, permA);
            asm volatile("cp.async.commit_group;" ::: "memory");
        }
#pragma unroll
        for (int ks = 0; ks < 4; ++ks) {
            uint32_t bf[2][4];
#pragma unroll
            for (int in2 = 0; in2 < 2; ++in2)
                ldmatrix_x4(bf[in2], sb + F16_WH + SWZ128((uint32_t)(
                    (wn * 32 + in2 * 16 + lrow) * 128 + ks * 32 + lcol)));
            uint32_t ah[4][4], al[4][4];
#pragma unroll
            for (int im = 0; im < 4; ++im) {
                uint32_t off = SWZ128((uint32_t)(
                    (wm * 64 + im * 16 + lrow) * 128 + ks * 32 + lcol));
                ldmatrix_x4(ah[im], sb + F16_AH + off);
                ldmatrix_x4(al[im], sb + F16_AL + off);
            }
#pragma unroll
            for (int im = 0; im < 4; ++im)
#pragma unroll
                for (int in = 0; in < 4; ++in) {
                    uint32_t b0 = bf[in >> 1][in & 1];
                    uint32_t b1 = bf[in >> 1][2 + (in & 1)];
                    mma_f16(acc[im][in], ah[im], b0, b1);
                    mma_f16(acc[im][in], al[im], b0, b1);
                }
        }
    }

    // epilogue
#pragma unroll
    for (int im = 0; im < 4; ++im) {
        int m  = m0 + wm * 64 + im * 16 + (lane >> 2);
        int r0 = permC ? swap66(m)     : m;
        int r1 = permC ? swap66(m + 8) : (m + 8);
#pragma unroll
        for (int in = 0; in < 4; ++in) {
            int n = n0 + wn * 32 + in * 8 + (lane & 3) * 2;
            if (n < N) {
                float2 v0 = make_float2(acc[im][in][0], acc[im][in][1]);
                float2 v1 = make_float2(acc[im][in][2], acc[im][in][3]);
                if (bias) {
                    float b0 = bias[n], b1 = bias[n + 1];
                    v0.x += b0; v0.y += b1;
                    v1.x += b0; v1.y += b1;
                }
                *(float2*)(C + (size_t)r0 * ldc + col0 + n) = v0;
                *(float2*)(C + (size_t)r1 * ldc + col0 + n) = v1;
            }
        }
    }
}

// ---------------------------------------------------------------------------
// Depthwise causal conv (width 4) + SiLU. Thread = (seq, t-chunk of 16, 4 ch).
// ---------------------------------------------------------------------------
#define C4N (CONV_DIM / 4)
__global__ void conv_silu_kernel(const float* __restrict__ zx,
                                 const float* __restrict__ cw,
                                 const float* __restrict__ cb,
                                 float* __restrict__ xbc)
{
    int idx = blockIdx.x * blockDim.x + threadIdx.x;
    if (idx >= NSEQ * 4 * C4N) return;
    int c4  = idx % C4N;
    int tmp = idx / C4N;
    int tc  = tmp & 3;
    int seq = tmp >> 2;
    int c   = c4 * 4;
    int t0  = tc * 16;

    float4 w[4];
#pragma unroll
    for (int j = 0; j < 4; ++j) w[j] = *(const float4*)(cw + (c + j) * 4);
    float4 b = *(const float4*)(cb + c);

    size_t ibase = (size_t)seq * LSEQ * D_IN_PROJ + D_INNER + c;
    size_t obase = (size_t)seq * LSEQ * CONV_DIM + c;

    float4 zero = make_float4(0.f, 0.f, 0.f, 0.f);
    float4 x0, x1, x2;
    if (t0 == 0) { x0 = zero; x1 = zero; x2 = zero; }
    else {
        x0 = *(const float4*)(zx + ibase + (size_t)(t0 - 3) * D_IN_PROJ);
        x1 = *(const float4*)(zx + ibase + (size_t)(t0 - 2) * D_IN_PROJ);
        x2 = *(const float4*)(zx + ibase + (size_t)(t0 - 1) * D_IN_PROJ);
    }
#pragma unroll
    for (int t = 0; t < 16; ++t) {
        float4 xt = *(const float4*)(zx + ibase + (size_t)(t0 + t) * D_IN_PROJ);
        float4 v;
        v.x = fmaf(x0.x, w[0].x, fmaf(x1.x, w[0].y, fmaf(x2.x, w[0].z, fmaf(xt.x, w[0].w, b.x))));
        v.y = fmaf(x0.y, w[1].x, fmaf(x1.y, w[1].y, fmaf(x2.y, w[1].z, fmaf(xt.y, w[1].w, b.y))));
        v.z = fmaf(x0.z, w[2].x, fmaf(x1.z, w[2].y, fmaf(x2.z, w[2].z, fmaf(xt.z, w[2].w, b.z))));
        v.w = fmaf(x0.w, w[3].x, fmaf(x1.w, w[3].y, fmaf(x2.w, w[3].z, fmaf(xt.w, w[3].w, b.w))));
        v.x = v.x / (1.f + expf(-v.x));
        v.y = v.y / (1.f + expf(-v.y));
        v.z = v.z / (1.f + expf(-v.z));
        v.w = v.w / (1.f + expf(-v.w));
        *(float4*)(xbc + obase + (size_t)(t0 + t) * CONV_DIM) = v;
        x0 = x1; x1 = x2; x2 = xt;
    }
}

// ---------------------------------------------------------------------------
// SSM kernel: register-tiled 4x4 per thread, float4 smem loads.
// ---------------------------------------------------------------------------
#define BCS 132
#define XSS 68
#define SSM_SMEM_FLOATS (2 * 64 * BCS + 2 * 64 * XSS + 128)
#define SSM_SMEM_BYTES  (SSM_SMEM_FLOATS * 4)

__global__ __launch_bounds__(256)
void ssm_kernel(const float* __restrict__ zx, const float* __restrict__ xbc,
                const float* __restrict__ A_log, const float* __restrict__ dt_bias,
                const float* __restrict__ Dp, float* __restrict__ y)
{
    extern __shared__ float sm[];
    float* Bs  = sm;
    float* Cs  = Bs + 64 * BCS;
    float* xs  = Cs + 64 * BCS;
    float* Wts = xs + 64 * XSS;
    float* dts = Wts + 64 * XSS;
    float* css = dts + 64;

    const int seq = blockIdx.x >> 4;
    const int h   = blockIdx.x & 15;
    const int tid = threadIdx.x;

    for (int i = tid; i < 64 * 128; i += 256) {
        int t = i >> 7, n = i & 127;
        size_t base = (size_t)(seq * LSEQ + t) * CONV_DIM;
        Bs[t * BCS + n] = xbc[base + D_INNER + n];
        Cs[t * BCS + n] = xbc[base + D_INNER + D_STATE + n];
    }
    for (int i = tid; i < 64 * 64; i += 256) {
        int t = i >> 6, p = i & 63;
        xs[t * XSS + p] = xbc[(size_t)(seq * LSEQ + t) * CONV_DIM + h * HEADDIM + p];
    }
    if (tid < 64) {
        float raw = zx[(size_t)(seq * LSEQ + tid) * D_IN_PROJ + (D_INNER + CONV_DIM) + h]
                    + dt_bias[h];
        dts[tid] = (raw > 20.f) ? raw : log1pf(expf(raw));
    }
    __syncthreads();
    if (tid == 0) {
        float a = -expf(A_log[h]);
        float run = 0.f;
        for (int t = 0; t < 64; ++t) { run += dts[t] * a; css[t] = run; }
    }
    __syncthreads();

    const int tt = (tid >> 4) << 2;
    const int ss = (tid & 15) << 2;

    float wa[4][4];
#pragma unroll
    for (int i = 0; i < 4; ++i)
#pragma unroll
        for (int j = 0; j < 4; ++j) wa[i][j] = 0.f;

    if (ss <= tt + 3) {
        for (int n = 0; n < 128; n += 4) {
            float4 cr[4], br[4];
#pragma unroll
            for (int i = 0; i < 4; ++i) cr[i] = *(const float4*)&Cs[(tt + i) * BCS + n];
#pragma unroll
            for (int j = 0; j < 4; ++j) br[j] = *(const float4*)&Bs[(ss + j) * BCS + n];
#pragma unroll
            for (int i = 0; i < 4; ++i)
#pragma unroll
                for (int j = 0; j < 4; ++j) {
                    wa[i][j] = fmaf(cr[i].x, br[j].x, wa[i][j]);
                    wa[i][j] = fmaf(cr[i].y, br[j].y, wa[i][j]);
                    wa[i][j] = fmaf(cr[i].z, br[j].z, wa[i][j]);
                    wa[i][j] = fmaf(cr[i].w, br[j].w, wa[i][j]);
                }
        }
    }
#pragma unroll
    for (int i = 0; i < 4; ++i)
#pragma unroll
        for (int j = 0; j < 4; ++j) {
            int t = tt + i, s = ss + j;
            float v = (s <= t) ? wa[i][j] * expf(css[t] - css[s]) * dts[s] : 0.f;
            Wts[t * XSS + s] = v;
        }
    __syncthreads();

    const float dcoef = Dp[h];
    float ya[4][4];
#pragma unroll
    for (int i = 0; i < 4; ++i) {
        float4 xv = *(const float4*)&xs[(tt + i) * XSS + ss];
        ya[i][0] = dcoef * xv.x; ya[i][1] = dcoef * xv.y;
        ya[i][2] = dcoef * xv.z; ya[i][3] = dcoef * xv.w;
    }
    for (int s0 = 0; s0 <= tt + 3; s0 += 4) {
        float4 wr[4], xr[4];
#pragma unroll
        for (int i = 0; i < 4; ++i) wr[i] = *(const float4*)&Wts[(tt + i) * XSS + s0];
#pragma unroll
        for (int k = 0; k < 4; ++k) xr[k] = *(const float4*)&xs[(s0 + k) * XSS + ss];
#pragma unroll
        for (int i = 0; i < 4; ++i) {
            ya[i][0] = fmaf(wr[i].x, xr[0].x, ya[i][0]);
            ya[i][1] = fmaf(wr[i].x, xr[0].y, ya[i][1]);
            ya[i][2] = fmaf(wr[i].x, xr[0].z, ya[i][2]);
            ya[i][3] = fmaf(wr[i].x, xr[0].w, ya[i][3]);
            ya[i][0] = fmaf(wr[i].y, xr[1].x, ya[i][0]);
            ya[i][1] = fmaf(wr[i].y, xr[1].y, ya[i][1]);
            ya[i][2] = fmaf(wr[i].y, xr[1].z, ya[i][2]);
            ya[i][3] = fmaf(wr[i].y, xr[1].w, ya[i][3]);
            ya[i][0] = fmaf(wr[i].z, xr[2].x, ya[i][0]);
            ya[i][1] = fmaf(wr[i].z, xr[2].y, ya[i][1]);
            ya[i][2] = fmaf(wr[i].z, xr[2].z, ya[i][2]);
            ya[i][3] = fmaf(wr[i].z, xr[2].w, ya[i][3]);
            ya[i][0] = fmaf(wr[i].w, xr[3].x, ya[i][0]);
            ya[i][1] = fmaf(wr[i].w, xr[3].y, ya[i][1]);
            ya[i][2] = fmaf(wr[i].w, xr[3].z, ya[i][2]);
            ya[i][3] = fmaf(wr[i].w, xr[3].w, ya[i][3]);
        }
    }
#pragma unroll
    for (int i = 0; i < 4; ++i) {
        float4 v = make_float4(ya[i][0], ya[i][1], ya[i][2], ya[i][3]);
        *(float4*)&y[(size_t)(seq * LSEQ + tt + i) * D_INNER + h * HEADDIM + ss] = v;
    }
}

// ---------------------------------------------------------------------------
// Gated RMSNorm: y = rmsnorm(y * silu(z)) * norm_w, in place (fp32)
// ---------------------------------------------------------------------------
__global__ __launch_bounds__(256)
void gate_norm_kernel(const float* __restrict__ zx, const float* __restrict__ norm_w,
                      float* __restrict__ y)
{
    const int row = blockIdx.x;
    const int tid = threadIdx.x;
    __shared__ float red[256];

    float vals[4];
    float ss = 0.f;
#pragma unroll
    for (int i = 0; i < 4; ++i) {
        int c = tid + i * 256;
        float z = zx[(size_t)row * D_IN_PROJ + c];
        float g = y[(size_t)row * D_INNER + c] * (z / (1.f + expf(-z)));
        vals[i] = g;
        ss += g * g;
    }
    red[tid] = ss;
    __syncthreads();
    for (int off = 128; off > 0; off >>= 1) {
        if (tid < off) red[tid] += red[tid + off];
        __syncthreads();
    }
    float scale = rsqrtf(red[0] / (float)D_INNER + EPS);
#pragma unroll
    for (int i = 0; i < 4; ++i) {
        int c = tid + i * 256;
        y[(size_t)row * D_INNER + c] = vals[i] * scale * norm_w[c];
    }
}

// ---------------------------------------------------------------------------
// fceff: pre-summed fc weights (out = [v|v|h|h] @ fc_w.T == [v|h] @ eff.T)
// ---------------------------------------------------------------------------
__global__ void fceff_kernel(const float* __restrict__ fc_w, float* __restrict__ eff)
{
    int idx = blockIdx.x * blockDim.x + threadIdx.x;
    if (idx >= D_MODEL * D_INNER) return;
    int o = idx >> 10;
    int j = idx & 1023;
    float v;
    if (j < 512) v = fc_w[(size_t)o * 2048 + j] + fc_w[(size_t)o * 2048 + 512 + j];
    else {
        int jj = j - 512;
        v = fc_w[(size_t)o * 2048 + 1024 + jj] + fc_w[(size_t)o * 2048 + 1536 + jj];
    }
    eff[idx] = v;
}

// ---------------------------------------------------------------------------
// Host side
// ---------------------------------------------------------------------------
extern "C" void kernel_launch(void* const* d_in, const int* in_sizes, int n_in,
                              void* d_out, int out_size)
{
    (void)in_sizes; (void)n_in; (void)out_size;
    const float* x        = (const float*)d_in[0];
    const float* h_in_w   = (const float*)d_in[1];
    const float* h_conv_w = (const float*)d_in[2];
    const float* h_conv_b = (const float*)d_in[3];
    const float* h_A_log  = (const float*)d_in[4];
    const float* h_dt_b   = (const float*)d_in[5];
    const float* h_D      = (const float*)d_in[6];
    const float* h_norm_w = (const float*)d_in[7];
    const float* h_out_w  = (const float*)d_in[8];
    const float* v_in_w   = (const float*)d_in[9];
    const float* v_conv_w = (const float*)d_in[10];
    const float* v_conv_b = (const float*)d_in[11];
    const float* v_A_log  = (const float*)d_in[12];
    const float* v_dt_b   = (const float*)d_in[13];
    const float* v_D      = (const float*)d_in[14];
    const float* v_norm_w = (const float*)d_in[15];
    const float* v_out_w  = (const float*)d_in[16];
    const float* fc_w     = (const float*)d_in[17];
    const float* fc_b     = (const float*)d_in[18];
    float* out = (float*)d_out;

    float *zx, *xbc, *y, *cat, *fceff;
    cudaGetSymbolAddress((void**)&zx,    g_zx);
    cudaGetSymbolAddress((void**)&xbc,   g_xbc);
    cudaGetSymbolAddress((void**)&y,     g_y);
    cudaGetSymbolAddress((void**)&cat,   g_cat);
    cudaGetSymbolAddress((void**)&fceff, g_fceff);

    cudaFuncSetAttribute(ssm_kernel, cudaFuncAttributeMaxDynamicSharedMemorySize,
                         SSM_SMEM_BYTES);
    cudaFuncSetAttribute(gemm_split_kernel, cudaFuncAttributeMaxDynamicSharedMemorySize,
                         GSM_TOTAL);

    const int TPB = 256;
    fceff_kernel<<<(D_MODEL * D_INNER + TPB - 1) / TPB, TPB>>>(fc_w, fceff);

    for (int dir = 0; dir < 2; ++dir) {
        const float* in_w   = dir ? v_in_w   : h_in_w;
        const float* conv_w = dir ? v_conv_w : h_conv_w;
        const float* conv_b = dir ? v_conv_b : h_conv_b;
        const float* A_log  = dir ? v_A_log  : h_A_log;
        const float* dt_b   = dir ? v_dt_b   : h_dt_b;
        const float* Dp     = dir ? v_D      : h_D;
        const float* norm_w = dir ? v_norm_w : h_norm_w;
        const float* out_w  = dir ? v_out_w  : h_out_w;

        // in-proj: A = x (v-dir: permuted rows), K=512, N=2320
        {
            dim3 g((D_IN_PROJ + 127) / 128, NTOK / 128);
            gemm_split_kernel<<<g, 256, GSM_TOTAL>>>(x, in_w, zx, 512, D_IN_PROJ,
                                                     D_IN_PROJ, 0, nullptr, dir, 0);
        }
        conv_silu_kernel<<<(NSEQ * 4 * C4N + TPB - 1) / TPB, TPB>>>(zx, conv_w, conv_b, xbc);
        ssm_kernel<<<NSEQ * NHEADS, 256, SSM_SMEM_BYTES>>>(zx, xbc, A_log, dt_b, Dp, y);
        gate_norm_kernel<<<NTOK, 256>>>(zx, norm_w, y);

        // out-proj: K=1024, N=512 -> write into cat slice
        // v-dir: cols 0..511, permuted rows; h-dir: cols 512..1023
        {
            dim3 g(512 / 128, NTOK / 128);
            gemm_split_kernel<<<g, 256, GSM_TOTAL>>>(y, out_w, cat, 1024, 512,
                                                     1024, dir ? 0 : 512, nullptr,
                                                     0, dir ? 1 : 0);
        }
    }

    // final fc: K=1024, N=512, bias
    {
        dim3 g(512 / 128, NTOK / 128);
        gemm_split_kernel<<<g, 256, GSM_TOTAL>>>(cat, fceff, out, 1024, 512,
                                                 512, 0, fc_b, 0, 0);
    }
}

// round 6
// speedup vs baseline: 1.4656x; 1.4656x over previous
#include <cuda_runtime.h>
#include <cuda_fp16.h>
#include <math.h>
#include <stdint.h>

// ---------------------------------------------------------------------------
// Problem constants
// ---------------------------------------------------------------------------
#define D_MODEL   512
#define D_STATE   128
#define HEADDIM   64
#define D_INNER   1024
#define NHEADS    16
#define CONV_DIM  1280
#define D_IN_PROJ 2320
#define LSEQ      64
#define NSEQ      128
#define NTOK      8192
#define EPS       1e-5f

#define NPAD_IN   2432            // D_IN_PROJ padded to multiple of 128

// ---------------------------------------------------------------------------
// Device scratch
// ---------------------------------------------------------------------------
__device__ float g_zx   [(size_t)NTOK * D_IN_PROJ];
__device__ float g_xbc  [(size_t)NTOK * CONV_DIM];
__device__ float g_y    [(size_t)NTOK * D_INNER];
__device__ float g_fceff[(size_t)D_MODEL * D_INNER];
__device__ __half g_asplitA[(size_t)NTOK * 2 * D_INNER];   // GEMM input splits
__device__ __half g_asplitB[(size_t)NTOK * 2 * D_INNER];   // cat split (fc input)
__device__ __half g_wsplit [(size_t)NPAD_IN * 2 * D_MODEL];

// ---------------------------------------------------------------------------
// Helpers
// ---------------------------------------------------------------------------
__device__ __forceinline__ uint32_t smem_u32(const void* p) {
    uint32_t a;
    asm("{ .reg .u64 t; cvta.to.shared.u64 t, %1; cvt.u32.u64 %0, t; }"
        : "=r"(a) : "l"(p));
    return a;
}
#define SWZ128(o) ((o) ^ (((o) >> 3) & 0x70))
#define CP_ASYNC16(dst, src) \
    asm volatile("cp.async.cg.shared.global [%0], [%1], 16;" :: "r"(dst), "l"(src) : "memory")

__device__ __forceinline__ void ldmatrix_x4(uint32_t* r, uint32_t addr) {
    asm volatile("ldmatrix.sync.aligned.m8n8.x4.shared.b16 {%0,%1,%2,%3}, [%4];"
                 : "=r"(r[0]), "=r"(r[1]), "=r"(r[2]), "=r"(r[3]) : "r"(addr));
}
__device__ __forceinline__ void mma_f16(float* d, const uint32_t* a,
                                        uint32_t b0, uint32_t b1) {
    asm volatile(
        "mma.sync.aligned.m16n8k16.row.col.f32.f16.f16.f32 "
        "{%0,%1,%2,%3}, {%4,%5,%6,%7}, {%8,%9}, {%0,%1,%2,%3};"
        : "+f"(d[0]), "+f"(d[1]), "+f"(d[2]), "+f"(d[3])
        : "r"(a[0]), "r"(a[1]), "r"(a[2]), "r"(a[3]), "r"(b0), "r"(b1));
}
__device__ __forceinline__ void split2h(float a, __half& hi, __half& lo) {
    hi = __float2half_rn(a);
    lo = __float2half_rn(a - __half2float(hi));
}
// swap the two low 6-bit fields of a token row index ((b,w,hh) <-> (b,hh,w))
__device__ __forceinline__ int swap66(int r) {
    return (r & ~0xFFF) | ((r & 63) << 6) | ((r >> 6) & 63);
}

// ---------------------------------------------------------------------------
// mma.sync split-fp16 GEMM (round-4 mainloop): C = A' W'^T
// Tile 128x128x64(fp16), 256 threads, 3-stage cp.async pipeline, SW128 SMEM.
// Epilogue: fp32 (ldc/bias) OR fp16 hi/lo split into dsplit (+perm, +col0).
// ---------------------------------------------------------------------------
#define GST       32768
#define GSM_TOTAL (3 * GST)

__device__ __forceinline__ void gemm_load_tile(
    const __half* __restrict__ A, const __half* __restrict__ W,
    uint32_t sb, int m0, int n0, int K2, int kt, int stage, int tid)
{
    uint32_t a_dst = sb + stage * GST;
    uint32_t b_dst = a_dst + 16384;
#pragma unroll
    for (int j = 0; j < 4; ++j) {
        int idx = tid + j * 256;
        int row = idx >> 3, c = idx & 7;
        CP_ASYNC16(a_dst + SWZ128((uint32_t)(row * 128 + c * 16)),
                   A + ((size_t)(m0 + row) * K2 + kt * 64 + c * 8));
    }
#pragma unroll
    for (int j = 0; j < 4; ++j) {
        int idx = tid + j * 256;
        int row = idx >> 3, c = idx & 7;
        CP_ASYNC16(b_dst + SWZ128((uint32_t)(row * 128 + c * 16)),
                   W + ((size_t)(n0 + row) * K2 + kt * 64 + c * 8));
    }
}

__global__ __launch_bounds__(256)
void gemm_tc_kernel(const __half* __restrict__ A, const __half* __restrict__ W,
                    float* __restrict__ C, __half* __restrict__ dsplit,
                    int K2, int N, int ldc, int col0,
                    const float* __restrict__ bias, int permC)
{
    extern __shared__ char smem[];
    uint32_t sb = smem_u32(smem);
    const int tid  = threadIdx.x;
    const int wid  = tid >> 5;
    const int lane = tid & 31;
    const int wm   = wid & 1;
    const int wn   = wid >> 1;
    const int m0   = blockIdx.y * 128;
    const int n0   = blockIdx.x * 128;

    float acc[4][4][4];
#pragma unroll
    for (int i = 0; i < 4; ++i)
#pragma unroll
        for (int j = 0; j < 4; ++j) {
            acc[i][j][0] = 0.f; acc[i][j][1] = 0.f;
            acc[i][j][2] = 0.f; acc[i][j][3] = 0.f;
        }

    const int nK = K2 / 64;
    gemm_load_tile(A, W, sb, m0, n0, K2, 0, 0, tid);
    asm volatile("cp.async.commit_group;" ::: "memory");
    gemm_load_tile(A, W, sb, m0, n0, K2, 1, 1, tid);
    asm volatile("cp.async.commit_group;" ::: "memory");

    const int lrow = lane & 15;
    const int lcol = (lane >> 4) * 16;

    int stage = 0;
    for (int i = 0; i < nK; ++i) {
        if (i < nK - 1) asm volatile("cp.async.wait_group 1;" ::: "memory");
        else            asm volatile("cp.async.wait_group 0;" ::: "memory");
        __syncthreads();

        if (i + 2 < nK) {
            int s2 = stage + 2; if (s2 >= 3) s2 -= 3;
            gemm_load_tile(A, W, sb, m0, n0, K2, i + 2, s2, tid);
            asm volatile("cp.async.commit_group;" ::: "memory");
        }

        uint32_t aBase = sb + stage * GST;
        uint32_t bBase = aBase + 16384;
#pragma unroll
        for (int ks = 0; ks < 4; ++ks) {
            uint32_t af[4][4];
#pragma unroll
            for (int im = 0; im < 4; ++im)
                ldmatrix_x4(af[im], aBase + SWZ128((uint32_t)(
                    (wm * 64 + im * 16 + lrow) * 128 + ks * 32 + lcol)));
            uint32_t bf[2][4];
#pragma unroll
            for (int in2 = 0; in2 < 2; ++in2)
                ldmatrix_x4(bf[in2], bBase + SWZ128((uint32_t)(
                    (wn * 32 + in2 * 16 + lrow) * 128 + ks * 32 + lcol)));
#pragma unroll
            for (int im = 0; im < 4; ++im)
#pragma unroll
                for (int in = 0; in < 4; ++in) {
                    uint32_t b0 = bf[in >> 1][in & 1];
                    uint32_t b1 = bf[in >> 1][2 + (in & 1)];
                    mma_f16(acc[im][in], af[im], b0, b1);
                }
        }
        if (++stage == 3) stage = 0;
    }

    // epilogue
#pragma unroll
    for (int im = 0; im < 4; ++im) {
        int m  = m0 + wm * 64 + im * 16 + (lane >> 2);
        int r0 = permC ? swap66(m)     : m;
        int r1 = permC ? swap66(m + 8) : (m + 8);
#pragma unroll
        for (int in = 0; in < 4; ++in) {
            int n = n0 + wn * 32 + in * 8 + (lane & 3) * 2;
            if (n >= N) continue;
            float2 v0 = make_float2(acc[im][in][0], acc[im][in][1]);
            float2 v1 = make_float2(acc[im][in][2], acc[im][in][3]);
            if (dsplit) {
                __half h0, l0, h1, l1;
                split2h(v0.x, h0, l0); split2h(v0.y, h1, l1);
                *(__half2*)(dsplit + (size_t)r0 * 2048 + col0 + n) =
                    __halves2half2(h0, h1);
                *(__half2*)(dsplit + (size_t)r0 * 2048 + 1024 + col0 + n) =
                    __halves2half2(l0, l1);
                split2h(v1.x, h0, l0); split2h(v1.y, h1, l1);
                *(__half2*)(dsplit + (size_t)r1 * 2048 + col0 + n) =
                    __halves2half2(h0, h1);
                *(__half2*)(dsplit + (size_t)r1 * 2048 + 1024 + col0 + n) =
                    __halves2half2(l0, l1);
            } else {
                if (bias) {
                    float b0 = bias[n], b1 = bias[n + 1];
                    v0.x += b0; v0.y += b1;
                    v1.x += b0; v1.y += b1;
                }
                *(float2*)(C + (size_t)r0 * ldc + col0 + n) = v0;
                *(float2*)(C + (size_t)r1 * ldc + col0 + n) = v1;
            }
        }
    }
}

// ---------------------------------------------------------------------------
// split helpers: fp32 -> fp16 [hi | lo] (activations) / [wh | wh] (weights)
// ---------------------------------------------------------------------------
__global__ void split_act_h_kernel(const float* __restrict__ A, __half* __restrict__ out)
{
    size_t idx = (size_t)blockIdx.x * blockDim.x + threadIdx.x;
    if (idx >= (size_t)NTOK * 512) return;
    int m = (int)(idx >> 9), k = (int)(idx & 511);
    __half hi, lo; split2h(A[idx], hi, lo);
    size_t base = (size_t)m * 1024 + k;
    out[base] = hi; out[base + 512] = lo;
}

__global__ void split_act_v_kernel(const float* __restrict__ x, __half* __restrict__ out)
{
    size_t idx = (size_t)blockIdx.x * blockDim.x + threadIdx.x;
    if (idx >= (size_t)NTOK * 512) return;
    int rv = (int)(idx >> 9), k = (int)(idx & 511);
    float a = x[((size_t)swap66(rv) << 9) + k];
    __half hi, lo; split2h(a, hi, lo);
    size_t base = (size_t)rv * 1024 + k;
    out[base] = hi; out[base + 512] = lo;
}

__global__ void split_w_kernel(const float* __restrict__ W, __half* __restrict__ out,
                               int N, int Npad, int K)
{
    size_t idx = (size_t)blockIdx.x * blockDim.x + threadIdx.x;
    if (idx >= (size_t)Npad * K) return;
    int n = (int)(idx / K), k = (int)(idx - (size_t)n * K);
    float w = (n < N) ? W[(size_t)n * K + k] : 0.f;
    __half wh = __float2half_rn(w);
    size_t base = (size_t)n * 2 * K + k;
    out[base] = wh; out[base + K] = wh;
}

// ---------------------------------------------------------------------------
// Depthwise causal conv (width 4) + SiLU. Thread = (seq, t-chunk of 16, 4 ch).
// ---------------------------------------------------------------------------
#define C4N (CONV_DIM / 4)
__global__ void conv_silu_kernel(const float* __restrict__ zx,
                                 const float* __restrict__ cw,
                                 const float* __restrict__ cb,
                                 float* __restrict__ xbc)
{
    int idx = blockIdx.x * blockDim.x + threadIdx.x;
    if (idx >= NSEQ * 4 * C4N) return;
    int c4  = idx % C4N;
    int tmp = idx / C4N;
    int tc  = tmp & 3;
    int seq = tmp >> 2;
    int c   = c4 * 4;
    int t0  = tc * 16;

    float4 w[4];
#pragma unroll
    for (int j = 0; j < 4; ++j) w[j] = *(const float4*)(cw + (c + j) * 4);
    float4 b = *(const float4*)(cb + c);

    size_t ibase = (size_t)seq * LSEQ * D_IN_PROJ + D_INNER + c;
    size_t obase = (size_t)seq * LSEQ * CONV_DIM + c;

    float4 zero = make_float4(0.f, 0.f, 0.f, 0.f);
    float4 x0, x1, x2;
    if (t0 == 0) { x0 = zero; x1 = zero; x2 = zero; }
    else {
        x0 = *(const float4*)(zx + ibase + (size_t)(t0 - 3) * D_IN_PROJ);
        x1 = *(const float4*)(zx + ibase + (size_t)(t0 - 2) * D_IN_PROJ);
        x2 = *(const float4*)(zx + ibase + (size_t)(t0 - 1) * D_IN_PROJ);
    }
#pragma unroll
    for (int t = 0; t < 16; ++t) {
        float4 xt = *(const float4*)(zx + ibase + (size_t)(t0 + t) * D_IN_PROJ);
        float4 v;
        v.x = fmaf(x0.x, w[0].x, fmaf(x1.x, w[0].y, fmaf(x2.x, w[0].z, fmaf(xt.x, w[0].w, b.x))));
        v.y = fmaf(x0.y, w[1].x, fmaf(x1.y, w[1].y, fmaf(x2.y, w[1].z, fmaf(xt.y, w[1].w, b.y))));
        v.z = fmaf(x0.z, w[2].x, fmaf(x1.z, w[2].y, fmaf(x2.z, w[2].z, fmaf(xt.z, w[2].w, b.z))));
        v.w = fmaf(x0.w, w[3].x, fmaf(x1.w, w[3].y, fmaf(x2.w, w[3].z, fmaf(xt.w, w[3].w, b.w))));
        v.x = v.x / (1.f + expf(-v.x));
        v.y = v.y / (1.f + expf(-v.y));
        v.z = v.z / (1.f + expf(-v.z));
        v.w = v.w / (1.f + expf(-v.w));
        *(float4*)(xbc + obase + (size_t)(t0 + t) * CONV_DIM) = v;
        x0 = x1; x1 = x2; x2 = xt;
    }
}

// ---------------------------------------------------------------------------
// SSM kernel: register-tiled 4x4, B stored transposed for conflict-free LDS.
// ---------------------------------------------------------------------------
#define BCS 132
#define BTS 68
#define XSS 68
#define SSM_SMEM_FLOATS (64 * BCS + 128 * BTS + 2 * 64 * XSS + 128)
#define SSM_SMEM_BYTES  (SSM_SMEM_FLOATS * 4)

__global__ __launch_bounds__(256)
void ssm_kernel(const float* __restrict__ zx, const float* __restrict__ xbc,
                const float* __restrict__ A_log, const float* __restrict__ dt_bias,
                const float* __restrict__ Dp, float* __restrict__ y)
{
    extern __shared__ float sm[];
    float* Cs  = sm;                 // [t][n]  64 x BCS
    float* Bt  = Cs + 64 * BCS;      // [n][s] 128 x BTS
    float* xs  = Bt + 128 * BTS;     // [t][p]  64 x XSS
    float* Wts = xs + 64 * XSS;      // [t][s]  64 x XSS
    float* dts = Wts + 64 * XSS;
    float* css = dts + 64;

    const int seq = blockIdx.x >> 4;
    const int h   = blockIdx.x & 15;
    const int tid = threadIdx.x;

    for (int i = tid; i < 64 * 128; i += 256) {
        int t = i >> 7, n = i & 127;
        size_t base = (size_t)(seq * LSEQ + t) * CONV_DIM;
        Bt[n * BTS + t] = xbc[base + D_INNER + n];
        Cs[t * BCS + n] = xbc[base + D_INNER + D_STATE + n];
    }
    for (int i = tid; i < 64 * 64; i += 256) {
        int t = i >> 6, p = i & 63;
        xs[t * XSS + p] = xbc[(size_t)(seq * LSEQ + t) * CONV_DIM + h * HEADDIM + p];
    }
    if (tid < 64) {
        float raw = zx[(size_t)(seq * LSEQ + tid) * D_IN_PROJ + (D_INNER + CONV_DIM) + h]
                    + dt_bias[h];
        dts[tid] = (raw > 20.f) ? raw : log1pf(expf(raw));
    }
    __syncthreads();
    if (tid == 0) {
        float a = -expf(A_log[h]);
        float run = 0.f;
        for (int t = 0; t < 64; ++t) { run += dts[t] * a; css[t] = run; }
    }
    __syncthreads();

    const int tt = (tid >> 4) << 2;
    const int ss = (tid & 15) << 2;

    // Phase 1: W[t][s] = (C[t].B[s]) 4x4 tile; wa[i][j] = sum_n C[tt+i][n]*Bt[n][ss+j]
    float wa[4][4];
#pragma unroll
    for (int i = 0; i < 4; ++i)
#pragma unroll
        for (int j = 0; j < 4; ++j) wa[i][j] = 0.f;

    if (ss <= tt + 3) {
        for (int n = 0; n < 128; n += 4) {
            float4 cr[4], bt[4];
#pragma unroll
            for (int i = 0; i < 4; ++i) cr[i] = *(const float4*)&Cs[(tt + i) * BCS + n];
#pragma unroll
            for (int k = 0; k < 4; ++k) bt[k] = *(const float4*)&Bt[(n + k) * BTS + ss];
#pragma unroll
            for (int i = 0; i < 4; ++i) {
                wa[i][0] = fmaf(cr[i].x, bt[0].x, wa[i][0]);
                wa[i][1] = fmaf(cr[i].x, bt[0].y, wa[i][1]);
                wa[i][2] = fmaf(cr[i].x, bt[0].z, wa[i][2]);
                wa[i][3] = fmaf(cr[i].x, bt[0].w, wa[i][3]);
                wa[i][0] = fmaf(cr[i].y, bt[1].x, wa[i][0]);
                wa[i][1] = fmaf(cr[i].y, bt[1].y, wa[i][1]);
                wa[i][2] = fmaf(cr[i].y, bt[1].z, wa[i][2]);
                wa[i][3] = fmaf(cr[i].y, bt[1].w, wa[i][3]);
                wa[i][0] = fmaf(cr[i].z, bt[2].x, wa[i][0]);
                wa[i][1] = fmaf(cr[i].z, bt[2].y, wa[i][1]);
                wa[i][2] = fmaf(cr[i].z, bt[2].z, wa[i][2]);
                wa[i][3] = fmaf(cr[i].z, bt[2].w, wa[i][3]);
                wa[i][0] = fmaf(cr[i].w, bt[3].x, wa[i][0]);
                wa[i][1] = fmaf(cr[i].w, bt[3].y, wa[i][1]);
                wa[i][2] = fmaf(cr[i].w, bt[3].z, wa[i][2]);
                wa[i][3] = fmaf(cr[i].w, bt[3].w, wa[i][3]);
            }
        }
    }
#pragma unroll
    for (int i = 0; i < 4; ++i) {
        int t = tt + i;
        float4 wv;
        wv.x = (ss + 0 <= t) ? wa[i][0] * expf(css[t] - css[ss + 0]) * dts[ss + 0] : 0.f;
        wv.y = (ss + 1 <= t) ? wa[i][1] * expf(css[t] - css[ss + 1]) * dts[ss + 1] : 0.f;
        wv.z = (ss + 2 <= t) ? wa[i][2] * expf(css[t] - css[ss + 2]) * dts[ss + 2] : 0.f;
        wv.w = (ss + 3 <= t) ? wa[i][3] * expf(css[t] - css[ss + 3]) * dts[ss + 3] : 0.f;
        *(float4*)&Wts[t * XSS + ss] = wv;
    }
    __syncthreads();

    // Phase 2: y[t][p] 4x4 tile
    const float dcoef = Dp[h];
    float ya[4][4];
#pragma unroll
    for (int i = 0; i < 4; ++i) {
        float4 xv = *(const float4*)&xs[(tt + i) * XSS + ss];
        ya[i][0] = dcoef * xv.x; ya[i][1] = dcoef * xv.y;
        ya[i][2] = dcoef * xv.z; ya[i][3] = dcoef * xv.w;
    }
    for (int s0 = 0; s0 <= tt + 3; s0 += 4) {
        float4 wr[4], xr[4];
#pragma unroll
        for (int i = 0; i < 4; ++i) wr[i] = *(const float4*)&Wts[(tt + i) * XSS + s0];
#pragma unroll
        for (int k = 0; k < 4; ++k) xr[k] = *(const float4*)&xs[(s0 + k) * XSS + ss];
#pragma unroll
        for (int i = 0; i < 4; ++i) {
            ya[i][0] = fmaf(wr[i].x, xr[0].x, ya[i][0]);
            ya[i][1] = fmaf(wr[i].x, xr[0].y, ya[i][1]);
            ya[i][2] = fmaf(wr[i].x, xr[0].z, ya[i][2]);
            ya[i][3] = fmaf(wr[i].x, xr[0].w, ya[i][3]);
            ya[i][0] = fmaf(wr[i].y, xr[1].x, ya[i][0]);
            ya[i][1] = fmaf(wr[i].y, xr[1].y, ya[i][1]);
            ya[i][2] = fmaf(wr[i].y, xr[1].z, ya[i][2]);
            ya[i][3] = fmaf(wr[i].y, xr[1].w, ya[i][3]);
            ya[i][0] = fmaf(wr[i].z, xr[2].x, ya[i][0]);
            ya[i][1] = fmaf(wr[i].z, xr[2].y, ya[i][1]);
            ya[i][2] = fmaf(wr[i].z, xr[2].z, ya[i][2]);
            ya[i][3] = fmaf(wr[i].z, xr[2].w, ya[i][3]);
            ya[i][0] = fmaf(wr[i].w, xr[3].x, ya[i][0]);
            ya[i][1] = fmaf(wr[i].w, xr[3].y, ya[i][1]);
            ya[i][2] = fmaf(wr[i].w, xr[3].z, ya[i][2]);
            ya[i][3] = fmaf(wr[i].w, xr[3].w, ya[i][3]);
        }
    }
#pragma unroll
    for (int i = 0; i < 4; ++i) {
        float4 v = make_float4(ya[i][0], ya[i][1], ya[i][2], ya[i][3]);
        *(float4*)&y[(size_t)(seq * LSEQ + tt + i) * D_INNER + h * HEADDIM + ss] = v;
    }
}

// ---------------------------------------------------------------------------
// Gated RMSNorm fused with fp16 split emit -> asplitA
// ---------------------------------------------------------------------------
__global__ __launch_bounds__(256)
void gate_norm_split_kernel(const float* __restrict__ zx, const float* __restrict__ norm_w,
                            const float* __restrict__ y, __half* __restrict__ out)
{
    const int row = blockIdx.x;
    const int tid = threadIdx.x;
    __shared__ float red[256];

    float vals[4];
    float ss = 0.f;
#pragma unroll
    for (int i = 0; i < 4; ++i) {
        int c = tid + i * 256;
        float z = zx[(size_t)row * D_IN_PROJ + c];
        float g = y[(size_t)row * D_INNER + c] * (z / (1.f + expf(-z)));
        vals[i] = g;
        ss += g * g;
    }
    red[tid] = ss;
    __syncthreads();
    for (int off = 128; off > 0; off >>= 1) {
        if (tid < off) red[tid] += red[tid + off];
        __syncthreads();
    }
    float scale = rsqrtf(red[0] / (float)D_INNER + EPS);
#pragma unroll
    for (int i = 0; i < 4; ++i) {
        int c = tid + i * 256;
        float g = vals[i] * scale * norm_w[c];
        __half hi, lo; split2h(g, hi, lo);
        size_t base = (size_t)row * 2048 + c;
        out[base] = hi; out[base + 1024] = lo;
    }
}

// ---------------------------------------------------------------------------
// fceff: pre-summed fc weights
// ---------------------------------------------------------------------------
__global__ void fceff_kernel(const float* __restrict__ fc_w, float* __restrict__ eff)
{
    int idx = blockIdx.x * blockDim.x + threadIdx.x;
    if (idx >= D_MODEL * D_INNER) return;
    int o = idx >> 10;
    int j = idx & 1023;
    float v;
    if (j < 512) v = fc_w[(size_t)o * 2048 + j] + fc_w[(size_t)o * 2048 + 512 + j];
    else {
        int jj = j - 512;
        v = fc_w[(size_t)o * 2048 + 1024 + jj] + fc_w[(size_t)o * 2048 + 1536 + jj];
    }
    eff[idx] = v;
}

// ---------------------------------------------------------------------------
// Host side
// ---------------------------------------------------------------------------
extern "C" void kernel_launch(void* const* d_in, const int* in_sizes, int n_in,
                              void* d_out, int out_size)
{
    (void)in_sizes; (void)n_in; (void)out_size;
    const float* x        = (const float*)d_in[0];
    const float* h_in_w   = (const float*)d_in[1];
    const float* h_conv_w = (const float*)d_in[2];
    const float* h_conv_b = (const float*)d_in[3];
    const float* h_A_log  = (const float*)d_in[4];
    const float* h_dt_b   = (const float*)d_in[5];
    const float* h_D      = (const float*)d_in[6];
    const float* h_norm_w = (const float*)d_in[7];
    const float* h_out_w  = (const float*)d_in[8];
    const float* v_in_w   = (const float*)d_in[9];
    const float* v_conv_w = (const float*)d_in[10];
    const float* v_conv_b = (const float*)d_in[11];
    const float* v_A_log  = (const float*)d_in[12];
    const float* v_dt_b   = (const float*)d_in[13];
    const float* v_D      = (const float*)d_in[14];
    const float* v_norm_w = (const float*)d_in[15];
    const float* v_out_w  = (const float*)d_in[16];
    const float* fc_w     = (const float*)d_in[17];
    const float* fc_b     = (const float*)d_in[18];
    float* out = (float*)d_out;

    float *zx, *xbc, *y, *fceff;
    __half *asplitA, *asplitB, *wsplit;
    cudaGetSymbolAddress((void**)&zx,      g_zx);
    cudaGetSymbolAddress((void**)&xbc,     g_xbc);
    cudaGetSymbolAddress((void**)&y,       g_y);
    cudaGetSymbolAddress((void**)&fceff,   g_fceff);
    cudaGetSymbolAddress((void**)&asplitA, g_asplitA);
    cudaGetSymbolAddress((void**)&asplitB, g_asplitB);
    cudaGetSymbolAddress((void**)&wsplit,  g_wsplit);

    cudaFuncSetAttribute(ssm_kernel, cudaFuncAttributeMaxDynamicSharedMemorySize,
                         SSM_SMEM_BYTES);
    cudaFuncSetAttribute(gemm_tc_kernel, cudaFuncAttributeMaxDynamicSharedMemorySize,
                         GSM_TOTAL);

    const int TPB = 256;
    fceff_kernel<<<(D_MODEL * D_INNER + TPB - 1) / TPB, TPB>>>(fc_w, fceff);

    for (int dir = 0; dir < 2; ++dir) {
        const float* in_w   = dir ? v_in_w   : h_in_w;
        const float* conv_w = dir ? v_conv_w : h_conv_w;
        const float* conv_b = dir ? v_conv_b : h_conv_b;
        const float* A_log  = dir ? v_A_log  : h_A_log;
        const float* dt_b   = dir ? v_dt_b   : h_dt_b;
        const float* Dp     = dir ? v_D      : h_D;
        const float* norm_w = dir ? v_norm_w : h_norm_w;
        const float* out_w  = dir ? v_out_w  : h_out_w;

        // in-proj: K2=1024, N=2320 (padded 2432) -> zx fp32
        if (dir == 0)
            split_act_h_kernel<<<(NTOK * 512 + TPB - 1) / TPB, TPB>>>(x, asplitA);
        else
            split_act_v_kernel<<<(NTOK * 512 + TPB - 1) / TPB, TPB>>>(x, asplitA);
        split_w_kernel<<<(NPAD_IN * 512 + TPB - 1) / TPB, TPB>>>(in_w, wsplit,
                                                                 D_IN_PROJ, NPAD_IN, 512);
        {
            dim3 g(NPAD_IN / 128, NTOK / 128);
            gemm_tc_kernel<<<g, 256, GSM_TOTAL>>>(asplitA, wsplit, zx, nullptr,
                                                  1024, D_IN_PROJ, D_IN_PROJ, 0,
                                                  nullptr, 0);
        }

        conv_silu_kernel<<<(NSEQ * 4 * C4N + TPB - 1) / TPB, TPB>>>(zx, conv_w, conv_b, xbc);
        ssm_kernel<<<NSEQ * NHEADS, 256, SSM_SMEM_BYTES>>>(zx, xbc, A_log, dt_b, Dp, y);
        gate_norm_split_kernel<<<NTOK, 256>>>(zx, norm_w, y, asplitA);

        // out-proj: K2=2048, N=512 -> split epilogue into asplitB (cat layout)
        // v-dir: cols 0..511 with row permute; h-dir: cols 512..1023
        split_w_kernel<<<(512 * 1024 + TPB - 1) / TPB, TPB>>>(out_w, wsplit, 512, 512, 1024);
        {
            dim3 g(512 / 128, NTOK / 128);
            gemm_tc_kernel<<<g, 256, GSM_TOTAL>>>(asplitA, wsplit, nullptr, asplitB,
                                                  2048, 512, 0, dir ? 0 : 512,
                                                  nullptr, dir ? 1 : 0);
        }
    }

    // final fc: K2=2048, N=512, bias -> out fp32
    split_w_kernel<<<(512 * 1024 + TPB - 1) / TPB, TPB>>>(fceff, wsplit, 512, 512, 1024);
    {
        dim3 g(512 / 128, NTOK / 128);
        gemm_tc_kernel<<<g, 256, GSM_TOTAL>>>(asplitB, wsplit, out, nullptr,
                                              2048, 512, 512, 0, fc_b, 0);
    }
}